// round 7
// baseline (speedup 1.0000x reference)
#include <cuda_runtime.h>
#include <cuda_fp16.h>
#include <math.h>

#define HH 512
#define WW 512
#define NVIEW 768
#define NDCT 736
#define NT 725

#define PW 513
#define PH 514

// fp16 pair table: g_ph[py*PW+px] = { half2(c0,c1)@x=px-1, half2(c0,c1)@x=px },
// image row y = py-1, zero border. 8 bytes/entry.
struct __align__(8) HPair { __half2 lo, hi; };
__device__ HPair g_ph[PH * PW];

__global__ void build_pair(const float* __restrict__ in) {
    int i = blockIdx.x * blockDim.x + threadIdx.x;
    if (i >= PH * PW) return;
    int py = i / PW;
    int px = i - py * PW;
    int y = py - 1;
    int x0 = px - 1;
    float l0 = 0.0f, l1 = 0.0f, h0 = 0.0f, h1 = 0.0f;
    if (y >= 0 && y < HH) {
        if (x0 >= 0) {
            l0 = in[y * WW + x0];
            l1 = in[HH * WW + y * WW + x0];
        }
        if (px < WW) {
            h0 = in[y * WW + px];
            h1 = in[HH * WW + y * WW + px];
        }
    }
    HPair p;
    p.lo = __floats2half2_rn(l0, l1);
    p.hi = __floats2half2_rn(h0, h1);
    g_ph[i] = p;
}

// Clip t so x(t)=bx-sn*t, y(t)=by+c*t stay inside (-0.999, 511.999).
__device__ __forceinline__ void clip_ray(float bx, float by, float sn, float c,
                                         int& k0, int& k1) {
    float tlo = -362.0f, thi = 362.0f;
    const float lo = -0.999f;
    const float hi = 511.999f;
    if (sn > 1e-7f) {
        float inv = __frcp_rn(sn);
        tlo = fmaxf(tlo, (bx - hi) * inv);
        thi = fminf(thi, (bx - lo) * inv);
    } else if (bx <= lo || bx >= hi) {
        thi = tlo - 1.0f;
    }
    if (c > 1e-7f) {
        float inv = __frcp_rn(c);
        tlo = fmaxf(tlo, (lo - by) * inv);
        thi = fminf(thi, (hi - by) * inv);
    } else if (c < -1e-7f) {
        float inv = __frcp_rn(c);
        tlo = fmaxf(tlo, (hi - by) * inv);
        thi = fminf(thi, (lo - by) * inv);
    } else if (by <= lo || by >= hi) {
        thi = tlo - 1.0f;
    }
    k0 = max(0, (int)ceilf(tlo + 362.0f));
    k1 = min(NT - 1, (int)floorf(thi + 362.0f));
}

#define MAGIC 8388608.0f  // 2^23
#define DEAD_KB (1 << 30) // with span=0, unsigned predicate is always false

__device__ __forceinline__ void sample_h(float xp, float yp, __half2& pacc) {
    float sx = __fadd_rd(xp, MAGIC);
    float sy = __fadd_rd(yp, MAGIC);
    int ixp = __float_as_int(sx) & 0x7FFFFF;
    int iyp = __float_as_int(sy) & 0x7FFFFF;
    float wx = xp - (sx - MAGIC);
    float wy = yp - (sy - MAGIC);
    __half2 wxh = __float2half2_rn(wx);
    __half2 wyh = __float2half2_rn(wy);
    int base = iyp * PW + ixp;
    HPair r0 = g_ph[base];
    HPair r1 = g_ph[base + PW];
    __half2 a0 = __hfma2(wxh, __hsub2(r0.hi, r0.lo), r0.lo);
    __half2 a1 = __hfma2(wxh, __hsub2(r1.hi, r1.lo), r1.lo);
    __half2 val = __hfma2(wyh, __hsub2(a1, a0), a0);
    pacc = __hadd2(pacc, val);
}

__device__ __forceinline__ void ray_setup(int v, int s, float& sn, float& c,
                                          float& bxp, float& byp, int& k0, int& k1) {
    float theta = (float)v * (float)(M_PI / (double)NVIEW);
    sincosf(theta, &sn, &c);
    float sf = (float)s - 367.5f;
    float bx = fmaf(sf, c, 255.5f);
    float by = fmaf(sf, sn, 255.5f);
    clip_ray(bx, by, sn, c, k0, k1);
    bxp = bx + 1.0f;
    byp = by + 1.0f;
}

// Kernel A: views with |cos| >= sin (vy in [0,384] -> v in [0,192] U [576,767]).
// Block: 4 adjacent views x 16 detectors. Warp (8/block): view = w>>1,
// det-half = w&1; warp tile 8 det (si=lane&7) x 4 t-offsets (ti=lane>>3).
// Block-uniform k-chunks + syncthreads keep all warps in one moving ~15KB
// window of the table so L1 captures the 4x inter-view reuse.
__global__ void __launch_bounds__(256) radonA(float* __restrict__ out) {
    int lane = threadIdx.x & 31;
    int warp = threadIdx.x >> 5;
    int si = lane & 7;
    int ti = lane >> 3;
    int s = blockIdx.x * 16 + (warp & 1) * 8 + si;
    int vy = blockIdx.y * 4 + (warp >> 1);

    __shared__ int sK0, sK1;
    if (threadIdx.x == 0) { sK0 = NT; sK1 = -1; }
    __syncthreads();

    bool alive = (vy <= 384);
    int vyc = alive ? vy : 384;
    int v = (vyc < 193) ? vyc : (vyc + 383);

    float sn, c, bxp, byp;
    int k0, k1;
    ray_setup(v, s, sn, c, bxp, byp, k0, k1);

    int span, kb;
    if (alive && k0 <= k1) {
        atomicMin(&sK0, k0);
        atomicMax(&sK1, k1);
        span = k1 - k0;
    } else {
        span = 0;
        kb = DEAD_KB;
    }
    __syncthreads();
    int K0 = sK0, K1 = sK1;
    if (alive && k0 <= k1) kb = K0 + ti - k0;

    float accx = 0.0f, accy = 0.0f;
    float tf = (float)(K0 + ti) - 362.0f;

    for (int cb = K0; cb <= K1; cb += 32) {
        __half2 pacc = __float2half2_rn(0.0f);
        #pragma unroll
        for (int u = 0; u < 8; ++u) {
            if ((unsigned)(kb + 4 * u) <= (unsigned)span) {
                float tfu = tf + (float)(4 * u);
                float xp = fmaf(tfu, -sn, bxp);
                float yp = fmaf(tfu, c, byp);
                sample_h(xp, yp, pacc);
            }
        }
        float2 f = __half22float2(pacc);
        accx += f.x;
        accy += f.y;
        tf += 32.0f;
        kb += 32;
        __syncthreads();
    }

    accx += __shfl_xor_sync(0xFFFFFFFFu, accx, 8);
    accy += __shfl_xor_sync(0xFFFFFFFFu, accy, 8);
    accx += __shfl_xor_sync(0xFFFFFFFFu, accx, 16);
    accy += __shfl_xor_sync(0xFFFFFFFFu, accy, 16);
    if (lane < 8 && alive) {
        out[v * NDCT + s] = accx;
        out[NVIEW * NDCT + v * NDCT + s] = accy;
    }
}

// Kernel B: views with sin > |cos| (v in [193,575], 383 views).
// Block: 4 adjacent views x 8 detectors. Warp: view = w>>1, det-half = w&1;
// warp tile 4 det (si=lane&3) x 8 t-strides (ti=lane>>2).
__global__ void __launch_bounds__(256) radonB(float* __restrict__ out) {
    int lane = threadIdx.x & 31;
    int warp = threadIdx.x >> 5;
    int si = lane & 3;
    int ti = lane >> 2;
    int s = blockIdx.x * 8 + (warp & 1) * 4 + si;
    int vv = blockIdx.y * 4 + (warp >> 1);

    __shared__ int sK0, sK1;
    if (threadIdx.x == 0) { sK0 = NT; sK1 = -1; }
    __syncthreads();

    bool alive = (vv <= 382);
    int v = 193 + (alive ? vv : 382);

    float sn, c, bxp, byp;
    int k0, k1;
    ray_setup(v, s, sn, c, bxp, byp, k0, k1);

    int span, kb;
    if (alive && k0 <= k1) {
        atomicMin(&sK0, k0);
        atomicMax(&sK1, k1);
        span = k1 - k0;
    } else {
        span = 0;
        kb = DEAD_KB;
    }
    __syncthreads();
    int K0 = sK0, K1 = sK1;
    if (alive && k0 <= k1) kb = K0 + ti - k0;

    float accx = 0.0f, accy = 0.0f;
    float tf = (float)(K0 + ti) - 362.0f;

    for (int cb = K0; cb <= K1; cb += 32) {
        __half2 pacc = __float2half2_rn(0.0f);
        #pragma unroll
        for (int u = 0; u < 4; ++u) {
            if ((unsigned)(kb + 8 * u) <= (unsigned)span) {
                float tfu = tf + (float)(8 * u);
                float xp = fmaf(tfu, -sn, bxp);
                float yp = fmaf(tfu, c, byp);
                sample_h(xp, yp, pacc);
            }
        }
        float2 f = __half22float2(pacc);
        accx += f.x;
        accy += f.y;
        tf += 32.0f;
        kb += 32;
        __syncthreads();
    }

    accx += __shfl_xor_sync(0xFFFFFFFFu, accx, 4);
    accy += __shfl_xor_sync(0xFFFFFFFFu, accy, 4);
    accx += __shfl_xor_sync(0xFFFFFFFFu, accx, 8);
    accy += __shfl_xor_sync(0xFFFFFFFFu, accy, 8);
    accx += __shfl_xor_sync(0xFFFFFFFFu, accx, 16);
    accy += __shfl_xor_sync(0xFFFFFFFFu, accy, 16);
    if (lane < 4 && alive) {
        out[v * NDCT + s] = accx;
        out[NVIEW * NDCT + v * NDCT + s] = accy;
    }
}

extern "C" void kernel_launch(void* const* d_in, const int* in_sizes, int n_in,
                              void* d_out, int out_size) {
    const float* in = (const float*)d_in[0];
    float* out = (float*)d_out;

    build_pair<<<(PH * PW + 255) / 256, 256>>>(in);

    // A: 385 views in groups of 4 (97 groups), 16 det/block (46 blocks).
    dim3 gridA(NDCT / 16, 97);
    radonA<<<gridA, 256>>>(out);

    // B: 383 views in groups of 4 (96 groups), 8 det/block (92 blocks).
    dim3 gridB(NDCT / 8, 96);
    radonB<<<gridB, 256>>>(out);
}